// round 17
// baseline (speedup 1.0000x reference)
#include <cuda_runtime.h>
#include <cuda_bf16.h>
#include <math.h>
#include <stdint.h>

#define MAX_N 100000
#define MAX_E 1600000
#define D 64
#define TWO_D 128
#define SCAN_B 512
#define MAXNB ((MAX_N + SCAN_B - 1) / SCAN_B)   // 196

// Scratch (static __device__ arrays — no allocations allowed)
__device__ float4   g_srcv[MAX_N];               // (low_src, high_src, dnorm, 0)
__device__ float4   g_dstv[MAX_N];               // (low_dst, high_dst, dnorm, 0)
__device__ uint32_t g_zhi[(size_t)MAX_N * 64];   // z split-high, bf16x2 packed [node][64]
__device__ uint32_t g_zlo[(size_t)MAX_N * 64];   // z split-low,  bf16x2 packed
__device__ int      g_deg[MAX_N];
__device__ int      g_start[MAX_N];
__device__ int      g_cursor[MAX_N];
__device__ int      g_bsum[MAXNB + 1];
__device__ int      g_esrc[MAX_E];               // dst-grouped src indices

// ---------------------------------------------------------------------------
// bf16 split helpers + mma.sync (baseline PTX — no sm_103a features)
// ---------------------------------------------------------------------------
__device__ __forceinline__ void split2(float x, float y, uint32_t& hi, uint32_t& lo)
{
    __nv_bfloat16 hx = __float2bfloat16(x);
    __nv_bfloat16 hy = __float2bfloat16(y);
    float rx = x - __bfloat162float(hx);
    float ry = y - __bfloat162float(hy);
    __nv_bfloat162 H; H.x = hx; H.y = hy;
    __nv_bfloat162 L = __floats2bfloat162_rn(rx, ry);
    hi = *reinterpret_cast<uint32_t*>(&H);
    lo = *reinterpret_cast<uint32_t*>(&L);
}

__device__ __forceinline__ void split4(float4 v, uint2& hi, uint2& lo)
{
    split2(v.x, v.y, hi.x, lo.x);
    split2(v.z, v.w, hi.y, lo.y);
}

#define MMA_BF16(d, a0, a1, a2, a3, b0, b1) \
    asm volatile("mma.sync.aligned.m16n8k16.row.col.f32.bf16.bf16.f32 " \
        "{%0,%1,%2,%3}, {%4,%5,%6,%7}, {%8,%9}, {%0,%1,%2,%3};" \
        : "+f"((d)[0]), "+f"((d)[1]), "+f"((d)[2]), "+f"((d)[3]) \
        : "r"(a0), "r"(a1), "r"(a2), "r"(a3), "r"(b0), "r"(b1))

// ---------------------------------------------------------------------------
// Gate projections: one warp per node. Fused: deg zero.
// ---------------------------------------------------------------------------
__global__ void gate_kernel(const float* __restrict__ h,
                            const float* __restrict__ dnorm,
                            const float* __restrict__ Wl,
                            const float* __restrict__ Wh,
                            int n)
{
    int gtid = blockIdx.x * blockDim.x + threadIdx.x;
    if (gtid < n) g_deg[gtid] = 0;

    int warp = gtid >> 5;
    int lane = threadIdx.x & 31;
    if (warp >= n) return;

    const float* hp = h + (size_t)warp * D;
    float a0 = hp[lane];
    float a1 = hp[lane + 32];

    float ld = a0 * Wl[lane]      + a1 * Wl[lane + 32];
    float ls = a0 * Wl[lane + 64] + a1 * Wl[lane + 96];
    float hd = a0 * Wh[lane]      + a1 * Wh[lane + 32];
    float hs = a0 * Wh[lane + 64] + a1 * Wh[lane + 96];

    #pragma unroll
    for (int off = 16; off; off >>= 1) {
        ld += __shfl_xor_sync(0xFFFFFFFFu, ld, off);
        ls += __shfl_xor_sync(0xFFFFFFFFu, ls, off);
        hd += __shfl_xor_sync(0xFFFFFFFFu, hd, off);
        hs += __shfl_xor_sync(0xFFFFFFFFu, hs, off);
    }
    if (lane == 0) {
        float dn = dnorm[warp];
        g_srcv[warp] = make_float4(ls, hs, dn, 0.f);
        g_dstv[warp] = make_float4(ld, hd, dn, 0.f);
    }
}

// ---------------------------------------------------------------------------
__global__ void hist_kernel(const int* __restrict__ dst, int e)
{
    int i = blockIdx.x * blockDim.x + threadIdx.x;
    int e4 = e >> 2;
    if (i < e4) {
        int4 d4 = reinterpret_cast<const int4*>(dst)[i];
        atomicAdd(&g_deg[d4.x], 1);
        atomicAdd(&g_deg[d4.y], 1);
        atomicAdd(&g_deg[d4.z], 1);
        atomicAdd(&g_deg[d4.w], 1);
    }
    int t = e4 * 4 + i;
    if (i < (e & 3)) atomicAdd(&g_deg[dst[t]], 1);
}

// ---------------------------------------------------------------------------
__global__ void scan1_kernel(int n)
{
    __shared__ int swarp[16];
    int tid  = threadIdx.x;
    int lane = tid & 31;
    int wid  = tid >> 5;
    int i = blockIdx.x * SCAN_B + tid;
    int v = (i < n) ? g_deg[i] : 0;

    int x = v;
    #pragma unroll
    for (int off = 1; off < 32; off <<= 1) {
        int t = __shfl_up_sync(0xFFFFFFFFu, x, off);
        if (lane >= off) x += t;
    }
    if (lane == 31) swarp[wid] = x;
    __syncthreads();
    if (wid == 0) {
        int w = (lane < 16) ? swarp[lane] : 0;
        #pragma unroll
        for (int off = 1; off < 16; off <<= 1) {
            int t = __shfl_up_sync(0xFFFFFFFFu, w, off);
            if (lane >= off) w += t;
        }
        if (lane < 16) swarp[lane] = w;
    }
    __syncthreads();
    int wbase = (wid > 0) ? swarp[wid - 1] : 0;
    if (i < n) g_start[i] = wbase + x - v;
    if (tid == SCAN_B - 1) g_bsum[blockIdx.x] = wbase + x;
}

// ---------------------------------------------------------------------------
__global__ void scan3_kernel(int n, int nb)
{
    __shared__ int sb[MAXNB];
    __shared__ int swarp[8];
    int tid  = threadIdx.x;
    int lane = tid & 31;
    int wid  = tid >> 5;

    int v = (tid < nb) ? g_bsum[tid] : 0;
    int x = v;
    #pragma unroll
    for (int off = 1; off < 32; off <<= 1) {
        int t = __shfl_up_sync(0xFFFFFFFFu, x, off);
        if (lane >= off) x += t;
    }
    if (lane == 31) swarp[wid] = x;
    __syncthreads();
    if (wid == 0) {
        int w = (lane < 8) ? swarp[lane] : 0;
        #pragma unroll
        for (int off = 1; off < 8; off <<= 1) {
            int t = __shfl_up_sync(0xFFFFFFFFu, w, off);
            if (lane >= off) w += t;
        }
        if (lane < 8) swarp[lane] = w;
    }
    __syncthreads();
    int wbase = (wid > 0) ? swarp[wid - 1] : 0;
    if (tid < nb) sb[tid] = wbase + x - v;
    __syncthreads();

    int i = blockIdx.x * blockDim.x + tid;
    if (i < n) {
        int s = g_start[i] + sb[i / SCAN_B];
        g_start[i] = s;
        g_cursor[i] = s;
    }
}

// ---------------------------------------------------------------------------
__global__ void fill_kernel(const int* __restrict__ src,
                            const int* __restrict__ dst,
                            int e)
{
    int i = blockIdx.x * blockDim.x + threadIdx.x;
    if (i >= e) return;
    int pos = atomicAdd(&g_cursor[dst[i]], 1);
    g_esrc[pos] = src[i];
}

// ---------------------------------------------------------------------------
// Gather-aggregate v3: TWO nodes per warp (one per half-warp), lane owns
// a k-quad. Ends with in-register bf16 hi/lo split of z (once per node).
// ---------------------------------------------------------------------------
__global__ void gather_kernel(const float* __restrict__ h,
                              const float* __restrict__ bl,
                              const float* __restrict__ bh,
                              int n)
{
    int warp = (blockIdx.x * blockDim.x + threadIdx.x) >> 5;
    int lane = threadIdx.x & 31;
    int half = lane >> 4;
    int hl   = lane & 15;
    unsigned hmask = 0xFFFFu << (half * 16);
    int hbase = half << 4;

    int node = warp * 2 + half;
    bool valid = node < n;

    int start = 0, end = 0;
    float xl_base = 0.f, xh_base = 0.f, dn_t = 0.f;
    if (valid) {
        start = g_start[node];
        end   = start + g_deg[node];
        float4 dv = g_dstv[node];
        xl_base = dv.x + bl[0];
        xh_base = dv.y + bh[0];
        dn_t    = dv.z;
    }

    float4 zl = make_float4(0.f, 0.f, 0.f, 0.f);
    float4 zh = make_float4(0.f, 0.f, 0.f, 0.f);

    for (int base = start; base < end; base += 16) {
        int my = base + hl;
        int msrc = 0;
        float mel = 0.f, meh = 0.f;
        if (my < end) {
            msrc = g_esrc[my];
            float4 sv = g_srcv[msrc];
            float xl = xl_base + sv.x;
            float xh = xh_base + sv.y;
            float gl =  tanhf(xl > 0.f ? xl : -0.5f * xl);
            float gh = -tanhf(xh > 0.f ? xh : -0.5f * xh);
            float dd = dn_t * sv.z;
            mel = gl * dd;
            meh = gh * dd;
        }
        int cnt = min(16, end - base);

        int i = 0;
        for (; i + 4 <= cnt; i += 4) {
            int s0 = __shfl_sync(hmask, msrc, hbase + i);
            int s1 = __shfl_sync(hmask, msrc, hbase + i + 1);
            int s2 = __shfl_sync(hmask, msrc, hbase + i + 2);
            int s3 = __shfl_sync(hmask, msrc, hbase + i + 3);
            float cl0 = __shfl_sync(hmask, mel, hbase + i);
            float ch0 = __shfl_sync(hmask, meh, hbase + i);
            float cl1 = __shfl_sync(hmask, mel, hbase + i + 1);
            float ch1 = __shfl_sync(hmask, meh, hbase + i + 1);
            float cl2 = __shfl_sync(hmask, mel, hbase + i + 2);
            float ch2 = __shfl_sync(hmask, meh, hbase + i + 2);
            float cl3 = __shfl_sync(hmask, mel, hbase + i + 3);
            float ch3 = __shfl_sync(hmask, meh, hbase + i + 3);

            float4 v0 = reinterpret_cast<const float4*>(h + (size_t)s0 * D)[hl];
            float4 v1 = reinterpret_cast<const float4*>(h + (size_t)s1 * D)[hl];
            float4 v2 = reinterpret_cast<const float4*>(h + (size_t)s2 * D)[hl];
            float4 v3 = reinterpret_cast<const float4*>(h + (size_t)s3 * D)[hl];

            zl.x = fmaf(v0.x, cl0, zl.x); zl.y = fmaf(v0.y, cl0, zl.y);
            zl.z = fmaf(v0.z, cl0, zl.z); zl.w = fmaf(v0.w, cl0, zl.w);
            zh.x = fmaf(v0.x, ch0, zh.x); zh.y = fmaf(v0.y, ch0, zh.y);
            zh.z = fmaf(v0.z, ch0, zh.z); zh.w = fmaf(v0.w, ch0, zh.w);

            zl.x = fmaf(v1.x, cl1, zl.x); zl.y = fmaf(v1.y, cl1, zl.y);
            zl.z = fmaf(v1.z, cl1, zl.z); zl.w = fmaf(v1.w, cl1, zl.w);
            zh.x = fmaf(v1.x, ch1, zh.x); zh.y = fmaf(v1.y, ch1, zh.y);
            zh.z = fmaf(v1.z, ch1, zh.z); zh.w = fmaf(v1.w, ch1, zh.w);

            zl.x = fmaf(v2.x, cl2, zl.x); zl.y = fmaf(v2.y, cl2, zl.y);
            zl.z = fmaf(v2.z, cl2, zl.z); zl.w = fmaf(v2.w, cl2, zl.w);
            zh.x = fmaf(v2.x, ch2, zh.x); zh.y = fmaf(v2.y, ch2, zh.y);
            zh.z = fmaf(v2.z, ch2, zh.z); zh.w = fmaf(v2.w, ch2, zh.w);

            zl.x = fmaf(v3.x, cl3, zl.x); zl.y = fmaf(v3.y, cl3, zl.y);
            zl.z = fmaf(v3.z, cl3, zl.z); zl.w = fmaf(v3.w, cl3, zl.w);
            zh.x = fmaf(v3.x, ch3, zh.x); zh.y = fmaf(v3.y, ch3, zh.y);
            zh.z = fmaf(v3.z, ch3, zh.z); zh.w = fmaf(v3.w, ch3, zh.w);
        }
        for (; i < cnt; i++) {
            int s0   = __shfl_sync(hmask, msrc, hbase + i);
            float cl = __shfl_sync(hmask, mel,  hbase + i);
            float ch = __shfl_sync(hmask, meh,  hbase + i);
            float4 v0 = reinterpret_cast<const float4*>(h + (size_t)s0 * D)[hl];
            zl.x = fmaf(v0.x, cl, zl.x); zl.y = fmaf(v0.y, cl, zl.y);
            zl.z = fmaf(v0.z, cl, zl.z); zl.w = fmaf(v0.w, cl, zl.w);
            zh.x = fmaf(v0.x, ch, zh.x); zh.y = fmaf(v0.y, ch, zh.y);
            zh.z = fmaf(v0.z, ch, zh.z); zh.w = fmaf(v0.w, ch, zh.w);
        }
    }

    if (valid) {
        uint2 lhi, llo, hhi, hlo;
        split4(zl, lhi, llo);
        split4(zh, hhi, hlo);
        uint2* zhip = reinterpret_cast<uint2*>(g_zhi + (size_t)node * 64);
        uint2* zlop = reinterpret_cast<uint2*>(g_zlo + (size_t)node * 64);
        zhip[hl]      = lhi;     // low-half quad: k = 4hl
        zhip[16 + hl] = hhi;     // high-half quad: k = 64 + 4hl
        zlop[hl]      = llo;
        zlop[16 + hl] = hlo;
    }
}

// ---------------------------------------------------------------------------
// Output projection via mma.sync bf16 split-GEMM. A fragments load directly
// from pre-split g_zhi/g_zlo (no conversion ALU in this kernel).
// ---------------------------------------------------------------------------
__global__ void __launch_bounds__(256) out_mma_kernel(
    const float* __restrict__ Wr,
    const float* __restrict__ br,
    float* __restrict__ out,
    int n)
{
    __shared__ uint2 sBhi[2048];
    __shared__ uint2 sBlo[2048];

    int tid  = threadIdx.x;
    int lane = tid & 31;
    int w    = tid >> 5;
    int tg   = lane & 3;
    int g    = lane >> 2;

    for (int e = tid; e < 2048; e += 256) {
        int ln = e & 31;
        int kt = (e >> 5) & 7;
        int nt = e >> 8;
        int etg = ln & 3;
        int eg  = ln >> 2;
        int nrow = nt * 8 + eg;
        int k0 = kt * 16 + 2 * etg;
        float2 v0 = *reinterpret_cast<const float2*>(Wr + nrow * TWO_D + k0);
        float2 v1 = *reinterpret_cast<const float2*>(Wr + nrow * TWO_D + k0 + 8);
        uint32_t h0, l0, h1, l1;
        split2(v0.x, v0.y, h0, l0);
        split2(v1.x, v1.y, h1, l1);
        sBhi[e] = make_uint2(h0, h1);
        sBlo[e] = make_uint2(l0, l1);
    }
    __syncthreads();

    int m0 = blockIdx.x * 128 + w * 16;
    int r0 = m0 + g;
    int r1 = m0 + g + 8;
    bool p0 = r0 < n;
    bool p1 = r1 < n;

    float acc[8][4];
    #pragma unroll
    for (int nt = 0; nt < 8; nt++)
        #pragma unroll
        for (int q = 0; q < 4; q++)
            acc[nt][q] = 0.f;

    #pragma unroll
    for (int kt = 0; kt < 8; kt++) {
        int idx = kt * 8 + tg;   // uint32 index within node row (k0/2)

        uint32_t a0h = p0 ? g_zhi[(size_t)r0 * 64 + idx]     : 0u;
        uint32_t a2h = p0 ? g_zhi[(size_t)r0 * 64 + idx + 4] : 0u;
        uint32_t a1h = p1 ? g_zhi[(size_t)r1 * 64 + idx]     : 0u;
        uint32_t a3h = p1 ? g_zhi[(size_t)r1 * 64 + idx + 4] : 0u;
        uint32_t a0l = p0 ? g_zlo[(size_t)r0 * 64 + idx]     : 0u;
        uint32_t a2l = p0 ? g_zlo[(size_t)r0 * 64 + idx + 4] : 0u;
        uint32_t a1l = p1 ? g_zlo[(size_t)r1 * 64 + idx]     : 0u;
        uint32_t a3l = p1 ? g_zlo[(size_t)r1 * 64 + idx + 4] : 0u;

        #pragma unroll
        for (int nt = 0; nt < 8; nt++) {
            uint2 bh = sBhi[nt * 256 + kt * 32 + lane];
            uint2 bl = sBlo[nt * 256 + kt * 32 + lane];
            MMA_BF16(acc[nt], a0h, a1h, a2h, a3h, bh.x, bh.y);
            MMA_BF16(acc[nt], a0h, a1h, a2h, a3h, bl.x, bl.y);
            MMA_BF16(acc[nt], a0l, a1l, a2l, a3l, bh.x, bh.y);
        }
    }

    #pragma unroll
    for (int nt = 0; nt < 8; nt++) {
        int c0 = nt * 8 + 2 * tg;
        float2 b2 = *reinterpret_cast<const float2*>(br + c0);
        if (p0) {
            float2 o = make_float2(acc[nt][0] + b2.x, acc[nt][1] + b2.y);
            *reinterpret_cast<float2*>(out + (size_t)r0 * D + c0) = o;
        }
        if (p1) {
            float2 o = make_float2(acc[nt][2] + b2.x, acc[nt][3] + b2.y);
            *reinterpret_cast<float2*>(out + (size_t)r1 * D + c0) = o;
        }
    }
}

// ---------------------------------------------------------------------------
extern "C" void kernel_launch(void* const* d_in, const int* in_sizes, int n_in,
                              void* d_out, int out_size)
{
    const float* h   = (const float*)d_in[0];
    const float* dn  = (const float*)d_in[1];
    const int*   src = (const int*)  d_in[2];
    const int*   dst = (const int*)  d_in[3];
    const float* Wl  = (const float*)d_in[4];
    const float* bl  = (const float*)d_in[5];
    const float* Wh  = (const float*)d_in[6];
    const float* bh  = (const float*)d_in[7];
    const float* Wr  = (const float*)d_in[8];
    const float* br  = (const float*)d_in[9];
    float* out = (float*)d_out;

    int n = in_sizes[0] / D;      // nodes
    int e = in_sizes[2];          // edges
    int nb = (n + SCAN_B - 1) / SCAN_B;

    gate_kernel<<<(n * 32 + 255) / 256, 256>>>(h, dn, Wl, Wh, n);

    hist_kernel<<<((e >> 2) + 255) / 256, 256>>>(dst, e);
    scan1_kernel<<<nb, SCAN_B>>>(n);
    scan3_kernel<<<(n + 255) / 256, 256>>>(n, nb);
    fill_kernel<<<(e + 255) / 256, 256>>>(src, dst, e);

    int gwarps = (n + 1) / 2;
    gather_kernel<<<(int)(((size_t)gwarps * 32 + 255) / 256), 256>>>(h, bl, bh, n);

    out_mma_kernel<<<(n + 127) / 128, 256>>>(Wr, br, out, n);
}